// round 8
// baseline (speedup 1.0000x reference)
#include <cuda_runtime.h>
#include <cuda_bf16.h>

#define NN 100000
#define EE 1600000
#define DD 64
#define SCAN_BS 1024
#define SCAN_NB 98            // ceil(100000/1024)

// ------------- device scratch (no allocations allowed) ---------------------
__device__ __align__(16) float g_y[NN * DD];   // y = x @ W^T
__device__ float g_deg[NN];
__device__ float g_dinv[NN];
__device__ int   g_cnt[NN];           // per-row edge count
__device__ int   g_pos[NN];           // fill tickets
__device__ int   g_off[NN + 1];       // CSR row offsets
__device__ int   g_bsum[SCAN_NB];     // scan block sums
__device__ int   g_scol[EE];          // CSR col indices
__device__ float g_sw[EE];            // CSR weights (pre-scaled by dinv[col])

// ---------------------------------------------------------------------------
// K0: zero counters, deg = 1.0 (self loop)
__global__ void k_init(int n) {
    int i = blockIdx.x * blockDim.x + threadIdx.x;
    if (i < n) {
        g_cnt[i] = 0;
        g_pos[i] = 0;
        g_deg[i] = 1.0f;
    }
    if (i == 0) g_off[0] = 0;
}

// K1: per-edge: count rows, accumulate degree.  NOTE: edge_index is INT32.
__global__ void k_count(const int* __restrict__ rows,
                        const float* __restrict__ w, int e) {
    int i = blockIdx.x * blockDim.x + threadIdx.x;
    if (i < e) {
        int r = rows[i];
        atomicAdd(&g_cnt[r], 1);
        atomicAdd(&g_deg[r], w[i]);
    }
}

// K2a: per-block inclusive scan of g_cnt -> g_off[i+1], block totals -> g_bsum
__global__ __launch_bounds__(SCAN_BS) void k_scan1(int n) {
    __shared__ int s[SCAN_BS];
    int tid = threadIdx.x;
    int gid = blockIdx.x * SCAN_BS + tid;
    int v = (gid < n) ? g_cnt[gid] : 0;
    s[tid] = v;
    __syncthreads();
    #pragma unroll
    for (int off = 1; off < SCAN_BS; off <<= 1) {
        int t = (tid >= off) ? s[tid - off] : 0;
        __syncthreads();
        s[tid] += t;
        __syncthreads();
    }
    if (gid < n) g_off[gid + 1] = s[tid];
    if (tid == SCAN_BS - 1) g_bsum[blockIdx.x] = s[tid];
}

// K2b: serial exclusive scan of 98 block sums (trivial)
__global__ void k_scan2() {
    if (threadIdx.x == 0) {
        int run = 0;
        for (int b = 0; b < SCAN_NB; b++) {
            int t = g_bsum[b];
            g_bsum[b] = run;
            run += t;
        }
    }
}

// K2c: add block offsets; also compute dinv = deg^-1/2 (deg >= 1 always)
__global__ __launch_bounds__(SCAN_BS) void k_scan3(int n) {
    int gid = blockIdx.x * SCAN_BS + threadIdx.x;
    if (gid < n) {
        g_off[gid + 1] += g_bsum[blockIdx.x];
        g_dinv[gid] = rsqrtf(g_deg[gid]);
    }
}

// K3: scatter edges into CSR slots; pre-scale weight by dinv[col]
__global__ void k_fill(const int* __restrict__ rows,
                       const int* __restrict__ cols,
                       const float* __restrict__ w, int e) {
    int i = blockIdx.x * blockDim.x + threadIdx.x;
    if (i < e) {
        int r = rows[i];
        int c = cols[i];
        int slot = atomicAdd(&g_pos[r], 1);
        int idx = g_off[r] + slot;
        g_scol[idx] = c;
        g_sw[idx] = w[i] * g_dinv[c];
    }
}

// K4: y = x @ W^T   (M=100000, N=64, K=64), 64-row tiles (static smem 33 KB)
__global__ __launch_bounds__(256) void k_gemm(const float* __restrict__ x,
                                              const float* __restrict__ W,
                                              int n) {
    __shared__ float sX[64][65];   // padded: conflict-free column reads
    __shared__ float sW[64][64];   // broadcast reads: no padding needed
    int tid = threadIdx.x;
    int base = blockIdx.x * 64;

    #pragma unroll 4
    for (int idx = tid; idx < 64 * 64; idx += 256) {
        sW[idx >> 6][idx & 63] = W[idx];
        int r = idx >> 6, c = idx & 63;
        int gr = base + r;
        sX[r][c] = (gr < n) ? x[(size_t)gr * 64 + c] : 0.0f;
    }
    __syncthreads();

    int og = tid >> 5;   // 0..7  -> outputs [og*8, og*8+8)
    int ng = tid & 31;   // 0..31 -> nodes ng, ng+32

    float acc[2][8];
    #pragma unroll
    for (int i = 0; i < 2; i++)
        #pragma unroll
        for (int j = 0; j < 8; j++) acc[i][j] = 0.0f;

    #pragma unroll 4
    for (int k = 0; k < 64; k++) {
        float a0 = sX[ng][k];
        float a1 = sX[ng + 32][k];
        #pragma unroll
        for (int j = 0; j < 8; j++) {
            float wv = sW[og * 8 + j][k];
            acc[0][j] = fmaf(a0, wv, acc[0][j]);
            acc[1][j] = fmaf(a1, wv, acc[1][j]);
        }
    }

    #pragma unroll
    for (int i = 0; i < 2; i++) {
        int node = base + ng + 32 * i;
        if (node < n) {
            float4* p = (float4*)(g_y + (size_t)node * 64 + og * 8);
            p[0] = make_float4(acc[i][0], acc[i][1], acc[i][2], acc[i][3]);
            p[1] = make_float4(acc[i][4], acc[i][5], acc[i][6], acc[i][7]);
        }
    }
}

// K5: gather-SpMM. 16 lanes per row, one float4 per lane. No atomics.
// out[r] = dinv[r] * sum_e(sw_e * y[col_e]) + dinv[r]^2 * y[r] + b
__global__ __launch_bounds__(256) void k_gather(const float* __restrict__ b,
                                                float* __restrict__ out, int n) {
    int tid = threadIdx.x;
    int grp = tid >> 4;          // 0..15
    int c   = tid & 15;          // float4 column
    int r   = blockIdx.x * 16 + grp;
    if (r >= n) return;

    const float4* Y = (const float4*)g_y;
    int beg = g_off[r];
    int end = g_off[r + 1];

    float4 acc = make_float4(0.f, 0.f, 0.f, 0.f);
    int j = beg;
    for (; j + 1 < end; j += 2) {
        int   c0 = g_scol[j],   c1 = g_scol[j + 1];
        float w0 = g_sw[j],     w1 = g_sw[j + 1];
        float4 y0 = Y[(size_t)c0 * 16 + c];
        float4 y1 = Y[(size_t)c1 * 16 + c];
        acc.x = fmaf(w0, y0.x, acc.x); acc.y = fmaf(w0, y0.y, acc.y);
        acc.z = fmaf(w0, y0.z, acc.z); acc.w = fmaf(w0, y0.w, acc.w);
        acc.x = fmaf(w1, y1.x, acc.x); acc.y = fmaf(w1, y1.y, acc.y);
        acc.z = fmaf(w1, y1.z, acc.z); acc.w = fmaf(w1, y1.w, acc.w);
    }
    if (j < end) {
        int   c0 = g_scol[j];
        float w0 = g_sw[j];
        float4 y0 = Y[(size_t)c0 * 16 + c];
        acc.x = fmaf(w0, y0.x, acc.x); acc.y = fmaf(w0, y0.y, acc.y);
        acc.z = fmaf(w0, y0.z, acc.z); acc.w = fmaf(w0, y0.w, acc.w);
    }

    float dv = g_dinv[r];
    float s = dv * dv;
    float4 yr = Y[(size_t)r * 16 + c];
    float4 bv = ((const float4*)b)[c];
    float4 o;
    o.x = fmaf(dv, acc.x, fmaf(s, yr.x, bv.x));
    o.y = fmaf(dv, acc.y, fmaf(s, yr.y, bv.y));
    o.z = fmaf(dv, acc.z, fmaf(s, yr.z, bv.z));
    o.w = fmaf(dv, acc.w, fmaf(s, yr.w, bv.w));
    ((float4*)out)[(size_t)r * 16 + c] = o;
}

// ---------------------------------------------------------------------------
extern "C" void kernel_launch(void* const* d_in, const int* in_sizes, int n_in,
                              void* d_out, int out_size) {
    const float* x  = (const float*)d_in[0];
    const int*   ei = (const int*)d_in[1];     // INT32 [2, E] (JAX x64 disabled)
    const float* w  = (const float*)d_in[2];
    const float* W  = (const float*)d_in[3];
    const float* b  = (const float*)d_in[4];
    float* out = (float*)d_out;

    int n = in_sizes[0] / DD;       // 100000
    int e = in_sizes[2];            // 1600000
    const int* rows = ei;
    const int* cols = ei + e;

    const int T = 256;

    k_init <<<(n + T - 1) / T, T>>>(n);
    k_count<<<(e + T - 1) / T, T>>>(rows, w, e);
    k_scan1<<<SCAN_NB, SCAN_BS>>>(n);
    k_scan2<<<1, 32>>>();
    k_scan3<<<SCAN_NB, SCAN_BS>>>(n);
    k_fill <<<(e + T - 1) / T, T>>>(rows, cols, w, e);
    k_gemm <<<(n + 63) / 64, T>>>(x, W, n);
    k_gather<<<(n + 15) / 16, T>>>(b, out, n);
}

// round 9
// speedup vs baseline: 1.0946x; 1.0946x over previous
#include <cuda_runtime.h>
#include <cuda_bf16.h>

#define NN 100000
#define EE 1600000
#define DD 64
#define SCAN_BS 1024
#define SCAN_NB 98            // ceil(100000/1024)

struct __align__(8) Edge { int c; float w; };

// ------------- device scratch (no allocations allowed) ---------------------
__device__ __align__(16) float g_y[NN * DD];   // y = x @ W^T
__device__ float g_deg[NN];
__device__ float g_dinv[NN];
__device__ int   g_cnt[NN];           // per-row edge count
__device__ int   g_pos[NN];           // fill tickets
__device__ int   g_off[NN + 1];       // CSR row offsets
__device__ int   g_bsum[SCAN_NB];     // scan block sums
__device__ Edge  g_e[EE];             // CSR edges {col, w*dinv[col]}

// ---------------------------------------------------------------------------
// K0: zero counters, deg = 1.0 (self loop)
__global__ void k_init(int n) {
    int i = blockIdx.x * blockDim.x + threadIdx.x;
    if (i < n) {
        g_cnt[i] = 0;
        g_pos[i] = 0;
        g_deg[i] = 1.0f;
    }
    if (i == 0) g_off[0] = 0;
}

// K1: per-edge: count rows, accumulate degree (edge_index is INT32)
__global__ void k_count(const int* __restrict__ rows,
                        const float* __restrict__ w, int e) {
    int i = blockIdx.x * blockDim.x + threadIdx.x;
    if (i < e) {
        int r = rows[i];
        atomicAdd(&g_cnt[r], 1);
        atomicAdd(&g_deg[r], w[i]);
    }
}

// K2a: per-block inclusive scan of g_cnt -> g_off[i+1], block totals -> g_bsum
__global__ __launch_bounds__(SCAN_BS) void k_scan1(int n) {
    __shared__ int s[SCAN_BS];
    int tid = threadIdx.x;
    int gid = blockIdx.x * SCAN_BS + tid;
    int v = (gid < n) ? g_cnt[gid] : 0;
    s[tid] = v;
    __syncthreads();
    #pragma unroll
    for (int off = 1; off < SCAN_BS; off <<= 1) {
        int t = (tid >= off) ? s[tid - off] : 0;
        __syncthreads();
        s[tid] += t;
        __syncthreads();
    }
    if (gid < n) g_off[gid + 1] = s[tid];
    if (tid == SCAN_BS - 1) g_bsum[blockIdx.x] = s[tid];
}

// K2b: parallel exclusive scan of the 98 block sums (one 128-thread block)
__global__ void k_scan2() {
    __shared__ int s[128];
    int t = threadIdx.x;
    int v = (t < SCAN_NB) ? g_bsum[t] : 0;
    s[t] = v;
    __syncthreads();
    #pragma unroll
    for (int off = 1; off < 128; off <<= 1) {
        int u = (t >= off) ? s[t - off] : 0;
        __syncthreads();
        s[t] += u;
        __syncthreads();
    }
    if (t < SCAN_NB) g_bsum[t] = s[t] - v;   // exclusive
}

// K2c: add block offsets; also compute dinv = deg^-1/2 (deg >= 1 always)
__global__ __launch_bounds__(SCAN_BS) void k_scan3(int n) {
    int gid = blockIdx.x * SCAN_BS + threadIdx.x;
    if (gid < n) {
        g_off[gid + 1] += g_bsum[blockIdx.x];
        g_dinv[gid] = rsqrtf(g_deg[gid]);
    }
}

// K3: scatter edges into CSR slots; pre-scale weight by dinv[col]
__global__ void k_fill(const int* __restrict__ rows,
                       const int* __restrict__ cols,
                       const float* __restrict__ w, int e) {
    int i = blockIdx.x * blockDim.x + threadIdx.x;
    if (i < e) {
        int r = rows[i];
        int c = cols[i];
        int slot = atomicAdd(&g_pos[r], 1);
        Edge ed;
        ed.c = c;
        ed.w = w[i] * g_dinv[c];
        g_e[g_off[r] + slot] = ed;
    }
}

// K4: y = x @ W^T via packed fma.rn.f32x2 (full-rate fp32 on sm_103a).
// 64-node tile. Thread (og, ng) computes nodes {2ng, 2ng+1} x outs [og*8, og*8+8).
// Outputs are paired into f32x2 lanes; A value is splatted per node.
__global__ __launch_bounds__(256) void k_gemm(const float* __restrict__ x,
                                              const float* __restrict__ W,
                                              int n) {
    __shared__ float sXt[64 * 66];   // [k][r], pad 66: even stride for f32x2
    __shared__ float sWt[64 * 66];   // [k][o]
    int tid = threadIdx.x;
    int base = blockIdx.x * 64;

    #pragma unroll 4
    for (int idx = tid; idx < 64 * 64; idx += 256) {
        int r = idx >> 6, kk = idx & 63;          // for W: r == output o
        sWt[kk * 66 + r] = W[idx];                // transpose: W[o][k] -> sWt[k][o]
        int gr = base + r;
        sXt[kk * 66 + r] = (gr < n) ? x[(size_t)gr * 64 + kk] : 0.0f;
    }
    __syncthreads();

    int og = tid >> 5;   // 0..7  (uniform per warp)
    int ng = tid & 31;   // 0..31

    unsigned long long accA[4], accB[4];   // f32x2 accumulators: {out2p, out2p+1}
    #pragma unroll
    for (int j = 0; j < 4; j++) { accA[j] = 0ull; accB[j] = 0ull; }

    const float2* X2 = (const float2*)sXt;                       // stride 33
    const unsigned long long* W2 = (const unsigned long long*)sWt;

    #pragma unroll 4
    for (int k = 0; k < 64; k++) {
        float2 a = X2[k * 33 + ng];               // {x[2ng][k], x[2ng+1][k]}
        unsigned long long ax, ay;
        asm("mov.b64 %0, {%1,%1};" : "=l"(ax) : "f"(a.x));
        asm("mov.b64 %0, {%1,%1};" : "=l"(ay) : "f"(a.y));
        #pragma unroll
        for (int j = 0; j < 4; j++) {
            unsigned long long wp = W2[k * 33 + og * 4 + j];   // {W[2p][k],W[2p+1][k]}
            asm("fma.rn.f32x2 %0, %1, %2, %0;" : "+l"(accA[j]) : "l"(ax), "l"(wp));
            asm("fma.rn.f32x2 %0, %1, %2, %0;" : "+l"(accB[j]) : "l"(ay), "l"(wp));
        }
    }

    int node0 = base + 2 * ng;
    float o[8];
    if (node0 < n) {
        #pragma unroll
        for (int j = 0; j < 4; j++)
            asm("mov.b64 {%0,%1}, %2;" : "=f"(o[2*j]), "=f"(o[2*j+1]) : "l"(accA[j]));
        float4* p = (float4*)(g_y + (size_t)node0 * 64 + og * 8);
        p[0] = make_float4(o[0], o[1], o[2], o[3]);
        p[1] = make_float4(o[4], o[5], o[6], o[7]);
    }
    if (node0 + 1 < n) {
        #pragma unroll
        for (int j = 0; j < 4; j++)
            asm("mov.b64 {%0,%1}, %2;" : "=f"(o[2*j]), "=f"(o[2*j+1]) : "l"(accB[j]));
        float4* p = (float4*)(g_y + (size_t)(node0 + 1) * 64 + og * 8);
        p[0] = make_float4(o[0], o[1], o[2], o[3]);
        p[1] = make_float4(o[4], o[5], o[6], o[7]);
    }
}

// K5: gather-SpMM. 16 lanes per row, one float4 per lane. No atomics.
// out[r] = dinv[r] * sum_e(sw_e * y[col_e]) + dinv[r]^2 * y[r] + b
__global__ __launch_bounds__(256) void k_gather(const float* __restrict__ b,
                                                float* __restrict__ out, int n) {
    int tid = threadIdx.x;
    int grp = tid >> 4;          // 0..15
    int c   = tid & 15;          // float4 column
    int r   = blockIdx.x * 16 + grp;
    if (r >= n) return;

    const float4* Y = (const float4*)g_y;
    int beg = g_off[r];
    int end = g_off[r + 1];

    float4 acc = make_float4(0.f, 0.f, 0.f, 0.f);
    int j = beg;
    for (; j + 3 < end; j += 4) {
        Edge e0 = g_e[j],     e1 = g_e[j + 1];
        Edge e2 = g_e[j + 2], e3 = g_e[j + 3];
        float4 y0 = Y[(size_t)e0.c * 16 + c];
        float4 y1 = Y[(size_t)e1.c * 16 + c];
        float4 y2 = Y[(size_t)e2.c * 16 + c];
        float4 y3 = Y[(size_t)e3.c * 16 + c];
        acc.x = fmaf(e0.w, y0.x, acc.x); acc.y = fmaf(e0.w, y0.y, acc.y);
        acc.z = fmaf(e0.w, y0.z, acc.z); acc.w = fmaf(e0.w, y0.w, acc.w);
        acc.x = fmaf(e1.w, y1.x, acc.x); acc.y = fmaf(e1.w, y1.y, acc.y);
        acc.z = fmaf(e1.w, y1.z, acc.z); acc.w = fmaf(e1.w, y1.w, acc.w);
        acc.x = fmaf(e2.w, y2.x, acc.x); acc.y = fmaf(e2.w, y2.y, acc.y);
        acc.z = fmaf(e2.w, y2.z, acc.z); acc.w = fmaf(e2.w, y2.w, acc.w);
        acc.x = fmaf(e3.w, y3.x, acc.x); acc.y = fmaf(e3.w, y3.y, acc.y);
        acc.z = fmaf(e3.w, y3.z, acc.z); acc.w = fmaf(e3.w, y3.w, acc.w);
    }
    for (; j < end; j++) {
        Edge e0 = g_e[j];
        float4 y0 = Y[(size_t)e0.c * 16 + c];
        acc.x = fmaf(e0.w, y0.x, acc.x); acc.y = fmaf(e0.w, y0.y, acc.y);
        acc.z = fmaf(e0.w, y0.z, acc.z); acc.w = fmaf(e0.w, y0.w, acc.w);
    }

    float dv = g_dinv[r];
    float s = dv * dv;
    float4 yr = Y[(size_t)r * 16 + c];
    float4 bv = ((const float4*)b)[c];
    float4 o;
    o.x = fmaf(dv, acc.x, fmaf(s, yr.x, bv.x));
    o.y = fmaf(dv, acc.y, fmaf(s, yr.y, bv.y));
    o.z = fmaf(dv, acc.z, fmaf(s, yr.z, bv.z));
    o.w = fmaf(dv, acc.w, fmaf(s, yr.w, bv.w));
    ((float4*)out)[(size_t)r * 16 + c] = o;
}

// ---------------------------------------------------------------------------
extern "C" void kernel_launch(void* const* d_in, const int* in_sizes, int n_in,
                              void* d_out, int out_size) {
    const float* x  = (const float*)d_in[0];
    const int*   ei = (const int*)d_in[1];     // INT32 [2, E]
    const float* w  = (const float*)d_in[2];
    const float* W  = (const float*)d_in[3];
    const float* b  = (const float*)d_in[4];
    float* out = (float*)d_out;

    int n = in_sizes[0] / DD;       // 100000
    int e = in_sizes[2];            // 1600000
    const int* rows = ei;
    const int* cols = ei + e;

    // side stream + events for GEMM || CSR-build overlap (created once, before
    // the capture call; creation is host-side only, no device allocation)
    static cudaStream_t s2 = nullptr;
    static cudaEvent_t evFork = nullptr, evGemm = nullptr;
    if (!s2) {
        cudaStreamCreateWithFlags(&s2, cudaStreamNonBlocking);
        cudaEventCreateWithFlags(&evFork, cudaEventDisableTiming);
        cudaEventCreateWithFlags(&evGemm, cudaEventDisableTiming);
    }

    const int T = 256;

    // fork: GEMM runs concurrently with the CSR build
    cudaEventRecord(evFork, 0);
    cudaStreamWaitEvent(s2, evFork, 0);
    k_gemm<<<(n + 63) / 64, T, 0, s2>>>(x, W, n);
    cudaEventRecord(evGemm, s2);

    // main chain: CSR build
    k_init <<<(n + T - 1) / T, T>>>(n);
    k_count<<<(e + T - 1) / T, T>>>(rows, w, e);
    k_scan1<<<SCAN_NB, SCAN_BS>>>(n);
    k_scan2<<<1, 128>>>();
    k_scan3<<<SCAN_NB, SCAN_BS>>>(n);
    k_fill <<<(e + T - 1) / T, T>>>(rows, cols, w, e);

    // join, then gather
    cudaStreamWaitEvent(0, evGemm, 0);
    k_gather<<<(n + 15) / 16, T>>>(b, out, n);
}